// round 16
// baseline (speedup 1.0000x reference)
#include <cuda_runtime.h>
#include <cuda_fp16.h>
#include <cstdint>

#define BATCH 20
#define SEQ   4096
#define EMB   256
#define NB    32
#define BLK   128
#define CTX   384
#define MROWS (BATCH*SEQ)

// XOR-swizzled tiles (row-stride 32 words = 64 halves), no padding.
#define TILE128 16384                    // 128 rows x 32 words
#define TILE64  8192                     // 64 rows x 32 words
// fp32-acc kernels (v, av, out): 3-stage A(128) + 3-stage B(64)
#define BOFF3   (3*TILE128)
#define LSOFF3  (3*TILE128 + 3*TILE64)
#define SMEM_S  (LSOFF3 + 512)           // 74240 B -> 3 CTAs/SM
// fp16-acc kernels (qk12, qk): 2-stage A(128) + 2-stage B(64), 4 CTAs/SM
#define BOFFQ   (2*TILE128)
#define LSOFFQ  (2*TILE128 + 2*TILE64)
#define SMEM_Q  (LSOFFQ + 512)           // 49664 B -> 4 CTAs/SM

// Scratch (device globals; no allocations allowed)
__device__ __half g_xh[MROWS*EMB];
__device__ __half g_wh[4*EMB*EMB];                  // transposed fp16 weights [z][n][k]
__device__ __half g_qh[MROWS*EMB];
__device__ __half g_kh[MROWS*EMB];
__device__ __half g_vT[MROWS*EMB];                  // per 128-block [emb][token]
__device__ __half g_p [(size_t)BATCH*NB*BLK*CTX];   // exp(logits)
__device__ float  g_l [MROWS];
__device__ __half g_ah[MROWS*EMB];                  // attention out (permuted rows)

// ---- primitives -----------------------------------------------------------

__device__ __forceinline__ uint32_t smem_u32(const void* p) {
    uint32_t a;
    asm("{ .reg .u64 t; cvta.to.shared.u64 t, %1; cvt.u32.u64 %0, t; }"
        : "=r"(a) : "l"(p));
    return a;
}

__device__ __forceinline__ uint32_t f2h2(float a, float b) {
    __half2 h = __floats2half2_rn(a, b);
    return *(uint32_t*)&h;
}

__device__ __forceinline__ void cpa16(uint32_t dst, const void* src) {
    asm volatile("cp.async.cg.shared.global [%0], [%1], 16;" :: "r"(dst), "l"(src));
}
#define CP_COMMIT() asm volatile("cp.async.commit_group;" ::: "memory")
#define CP_WAIT1()  asm volatile("cp.async.wait_group 1;" ::: "memory")
#define CP_WAIT0()  asm volatile("cp.async.wait_group 0;" ::: "memory")

__device__ __forceinline__ void mma16h(float c[4], uint32_t a0, uint32_t a1,
                                       uint32_t a2, uint32_t a3,
                                       uint32_t b0, uint32_t b1) {
    asm volatile(
        "mma.sync.aligned.m16n8k16.row.col.f32.f16.f16.f32 "
        "{%0,%1,%2,%3}, {%4,%5,%6,%7}, {%8,%9}, {%0,%1,%2,%3};"
        : "+f"(c[0]), "+f"(c[1]), "+f"(c[2]), "+f"(c[3])
        : "r"(a0), "r"(a1), "r"(a2), "r"(a3), "r"(b0), "r"(b1));
}

// fp16-accumulate variant: D/C = 2 x .f16x2 regs
__device__ __forceinline__ void mma16hh(uint32_t c[2], uint32_t a0, uint32_t a1,
                                        uint32_t a2, uint32_t a3,
                                        uint32_t b0, uint32_t b1) {
    asm volatile(
        "mma.sync.aligned.m16n8k16.row.col.f16.f16.f16.f16 "
        "{%0,%1}, {%2,%3,%4,%5}, {%6,%7}, {%0,%1};"
        : "+r"(c[0]), "+r"(c[1])
        : "r"(a0), "r"(a1), "r"(a2), "r"(a3), "r"(b0), "r"(b1));
}

__device__ __forceinline__ void ldsm4(uint32_t r[4], uint32_t addr) {
    asm volatile("ldmatrix.sync.aligned.m8n8.x4.shared.b16 {%0,%1,%2,%3}, [%4];"
                 : "=r"(r[0]), "=r"(r[1]), "=r"(r[2]), "=r"(r[3]) : "r"(addr));
}

// swizzled word offset within a tile: row r, 4-word group gidx (0..7)
__device__ __forceinline__ uint32_t swz(int r, int gidx) {
    return (uint32_t)(r * 32 + ((gidx ^ (r & 7)) << 2));
}

// 128-row tile copy (4 x 16B/thread)
__device__ __forceinline__ void cpT128(uint32_t sD, const __half* __restrict__ src,
                                       int ldh, int t) {
#pragma unroll
    for (int j = 0; j < 4; j++) {
        int idx = j * 256 + t;
        int r = idx >> 3, seg = idx & 7;
        cpa16(sD + swz(r, seg) * 4, src + (size_t)r * ldh + seg * 8);
    }
}

// 64-row tile copy (2 x 16B/thread)
__device__ __forceinline__ void cpT64(uint32_t sD, const __half* __restrict__ src,
                                      int ldh, int t) {
#pragma unroll
    for (int j = 0; j < 2; j++) {
        int idx = j * 256 + t;
        int r = idx >> 3, seg = idx & 7;
        cpa16(sD + swz(r, seg) * 4, src + (size_t)r * ldh + seg * 8);
    }
}

// ---- 32x32 fp32-acc warp tile (v, av, out) --------------------------------

__device__ __forceinline__ void mma_chunk_32(uint32_t sA, uint32_t sB,
                                             float acc[8][4], int t) {
    int lane = t & 31, w = t >> 5;
    int rq = ((lane >> 3) & 1) * 8 + (lane & 7);
    int kg = (lane >> 4) & 1;
    int mrow0 = (w >> 1) * 32 + rq;
    int nrow0 = (w & 1) * 32 + rq;
#pragma unroll
    for (int s = 0; s < 4; s++) {
        uint32_t a[2][4], b[2][4];
#pragma unroll
        for (int mt = 0; mt < 2; mt++)
            ldsm4(a[mt], sA + swz(mrow0 + mt * 16, s * 2 + kg) * 4);
#pragma unroll
        for (int p = 0; p < 2; p++)
            ldsm4(b[p], sB + swz(nrow0 + p * 16, s * 2 + kg) * 4);
#pragma unroll
        for (int mt = 0; mt < 2; mt++)
#pragma unroll
            for (int nt = 0; nt < 4; nt++)
                mma16h(acc[mt * 4 + nt], a[mt][0], a[mt][1], a[mt][2], a[mt][3],
                       b[nt >> 1][nt & 1], b[nt >> 1][(nt & 1) + 2]);
    }
}

__device__ __forceinline__ void gemm3_32(const __half* __restrict__ Abase, int aStep, int lda,
                                         const __half* __restrict__ Bbase, int bStep, int ldb,
                                         int nC, float acc[8][4], char* smem, int t) {
    uint32_t aA[3], bA[3];
#pragma unroll
    for (int i = 0; i < 3; i++) {
        aA[i] = smem_u32(smem + i * TILE128);
        bA[i] = smem_u32(smem + BOFF3 + i * TILE64);
    }
    cpT128(aA[0], Abase, lda, t);
    cpT64(bA[0], Bbase, ldb, t);
    CP_COMMIT();
    cpT128(aA[1], Abase + aStep, lda, t);
    cpT64(bA[1], Bbase + bStep, ldb, t);
    CP_COMMIT();

    int bufc = 0, bufn = 2;
    for (int c = 0; c < nC; c++) {
        if (c < nC - 1) CP_WAIT1(); else CP_WAIT0();
        __syncthreads();
        if (c + 2 < nC) {
            cpT128(aA[bufn], Abase + (size_t)(c + 2) * aStep, lda, t);
            cpT64(bA[bufn], Bbase + (size_t)(c + 2) * bStep, ldb, t);
            CP_COMMIT();
        }
        mma_chunk_32(aA[bufc], bA[bufc], acc, t);
        bufc = (bufc == 2) ? 0 : bufc + 1;
        bufn = (bufn == 2) ? 0 : bufn + 1;
    }
}

// ---- 32x32 fp16-acc warp tile (qk12, qk): 4 CTAs/SM -----------------------

__device__ __forceinline__ void mma_chunk_32h(uint32_t sA, uint32_t sB,
                                              uint32_t acc[8][2], int t) {
    int lane = t & 31, w = t >> 5;
    int rq = ((lane >> 3) & 1) * 8 + (lane & 7);
    int kg = (lane >> 4) & 1;
    int mrow0 = (w >> 1) * 32 + rq;
    int nrow0 = (w & 1) * 32 + rq;
#pragma unroll
    for (int s = 0; s < 4; s++) {
        uint32_t a[2][4], b[2][4];
#pragma unroll
        for (int mt = 0; mt < 2; mt++)
            ldsm4(a[mt], sA + swz(mrow0 + mt * 16, s * 2 + kg) * 4);
#pragma unroll
        for (int p = 0; p < 2; p++)
            ldsm4(b[p], sB + swz(nrow0 + p * 16, s * 2 + kg) * 4);
#pragma unroll
        for (int mt = 0; mt < 2; mt++)
#pragma unroll
            for (int nt = 0; nt < 4; nt++)
                mma16hh(acc[mt * 4 + nt], a[mt][0], a[mt][1], a[mt][2], a[mt][3],
                        b[nt >> 1][nt & 1], b[nt >> 1][(nt & 1) + 2]);
    }
}

// 2-stage pipeline: A 128 rows, B 64 rows
__device__ __forceinline__ void gemm2_32h(const __half* __restrict__ Abase, int aStep, int lda,
                                          const __half* __restrict__ Bbase, int bStep, int ldb,
                                          int nC, uint32_t acc[8][2], char* smem, int t) {
    uint32_t aA[2], bA[2];
#pragma unroll
    for (int i = 0; i < 2; i++) {
        aA[i] = smem_u32(smem + i * TILE128);
        bA[i] = smem_u32(smem + BOFFQ + i * TILE64);
    }
    cpT128(aA[0], Abase, lda, t);
    cpT64(bA[0], Bbase, ldb, t);
    CP_COMMIT();

    for (int c = 0; c < nC; c++) {
        CP_WAIT0();
        __syncthreads();
        if (c + 1 < nC) {
            cpT128(aA[(c + 1) & 1], Abase + (size_t)(c + 1) * aStep, lda, t);
            cpT64(bA[(c + 1) & 1], Bbase + (size_t)(c + 1) * bStep, ldb, t);
            CP_COMMIT();
        }
        mma_chunk_32h(aA[c & 1], bA[c & 1], acc, t);
    }
}

// ---- kernel 0: fused cvt (x + W-transpose + l-init) -----------------------

#define XITEMS (MROWS*EMB/8)
#define WITEMS (4*EMB*EMB)
__global__ __launch_bounds__(256)
void cvt_all(const float* __restrict__ x,
             const float* __restrict__ Wq, const float* __restrict__ Wk,
             const float* __restrict__ Wv, const float* __restrict__ Wo) {
    int i = blockIdx.x * 256 + threadIdx.x;
    if (i < XITEMS) {
        float4 a = ((const float4*)x)[2 * i];
        float4 b = ((const float4*)x)[2 * i + 1];
        ((uint4*)g_xh)[i] = make_uint4(f2h2(a.x, a.y), f2h2(a.z, a.w),
                                       f2h2(b.x, b.y), f2h2(b.z, b.w));
        return;
    }
    int r = i - XITEMS;
    if (r < WITEMS) {
        int z = r >> 16, e = r & 65535;
        int k = e >> 8, n = e & 255;
        const float* src = (z == 0) ? Wq : (z == 1) ? Wk : (z == 2) ? Wv : Wo;
        g_wh[(size_t)z * EMB * EMB + n * EMB + k] = __float2half_rn(src[k * EMB + n]);
        return;
    }
    r -= WITEMS;
    if (r < MROWS) {
        int nbi = (r >> 7) & (NB - 1);
        g_l[r] = 128.0f * (float)((nbi == 0) + (nbi == NB - 1));  // exp(0) padded keys
    }
}

// ---- kernel 1: q,k projections (32x32 fp16 acc, 4/SM). grid (8, 640) ------

__global__ __launch_bounds__(256, 4)
void qk12_mma() {
    extern __shared__ char smbuf[];
    int t = threadIdx.x;
    int z = blockIdx.x >> 2, ntile = blockIdx.x & 3;
    int m0 = blockIdx.y * 128, n0 = ntile * 64;

    uint32_t acc[8][2] = {};
    gemm2_32h(g_xh + (size_t)m0 * EMB, 64, EMB,
              g_wh + (size_t)z * EMB * EMB + (size_t)n0 * EMB, 64, EMB,
              4, acc, smbuf, t);

    __half* C = (z == 0 ? g_qh : g_kh) + (size_t)m0 * EMB + n0;
    int lane = t & 31, w = t >> 5;
    int g = lane >> 2, tig = lane & 3;
    int mbase = (w >> 1) * 32 + g;
    int nbase = (w & 1) * 32 + 2 * tig;
#pragma unroll
    for (int mt = 0; mt < 2; mt++) {
#pragma unroll
        for (int nt = 0; nt < 4; nt++) {
            int m = mbase + mt * 16, n = nbase + nt * 8;
            *(uint32_t*)(C + (size_t)m * EMB + n)       = acc[mt * 4 + nt][0];
            *(uint32_t*)(C + (size_t)(m + 8) * EMB + n) = acc[mt * 4 + nt][1];
        }
    }
}

// ---- kernel 2: v projection (32x32, fp32 acc). grid (4 nt, 640) -----------

__global__ __launch_bounds__(256, 3)
void v_mma() {
    extern __shared__ char smbuf[];
    int t = threadIdx.x;
    int m0 = blockIdx.y * 128, n0 = blockIdx.x * 64;

    float acc[8][4] = {};
    gemm3_32(g_xh + (size_t)m0 * EMB, 64, EMB,
             g_wh + (size_t)2 * EMB * EMB + (size_t)n0 * EMB, 64, EMB,
             4, acc, smbuf, t);

    __half* VT = g_vT + (size_t)m0 * EMB + (size_t)n0 * 128;  // [emb][token]
    int lane = t & 31, w = t >> 5;
    int g = lane >> 2, tig = lane & 3;
    int mbase = (w >> 1) * 32 + g;
    int nbase = (w & 1) * 32 + 2 * tig;
#pragma unroll
    for (int mt = 0; mt < 2; mt++) {
#pragma unroll
        for (int nt = 0; nt < 4; nt++) {
            float* c4 = acc[mt * 4 + nt];
            int m = mbase + mt * 16, n = nbase + nt * 8;
            VT[(size_t)n * 128 + m]           = __float2half_rn(c4[0]);
            VT[(size_t)(n + 1) * 128 + m]     = __float2half_rn(c4[1]);
            VT[(size_t)n * 128 + m + 8]       = __float2half_rn(c4[2]);
            VT[(size_t)(n + 1) * 128 + m + 8] = __float2half_rn(c4[3]);
        }
    }
}

// ---- kernel 3: P = exp(Q@K^T/16) (32x32 fp16 acc, 4/SM). grid (6,NB,B) ----

__global__ __launch_bounds__(256, 4)
void qk_mma() {
    extern __shared__ char smbuf[];
    float* ls = (float*)(smbuf + LSOFFQ);
    int t = threadIdx.x;
    int cj = blockIdx.x >> 1, ntile = blockIdx.x & 1;
    int nbi = blockIdx.y, b = blockIdx.z;
    int gb = nbi + cj - 1;
    if (gb < 0 || gb >= NB) return;             // padded: handled in cvt_all

    if (t < 128) ls[t] = 0.f;                   // ordered by pipeline's first barrier
    int n0 = ntile * 64;

    uint32_t acc[8][2] = {};
    gemm2_32h(g_qh + (size_t)(b * SEQ + nbi * BLK) * EMB, 64, EMB,
              g_kh + (size_t)(b * SEQ + gb * BLK + n0) * EMB, 64, EMB,
              4, acc, smbuf, t);

    __half* P = g_p + ((size_t)(b * NB + nbi) * BLK) * CTX + cj * BLK + n0;
    int lane = t & 31, w = t >> 5;
    int g = lane >> 2, tig = lane & 3;
    int mbase = (w >> 1) * 32 + g;
    int nbase = (w & 1) * 32 + 2 * tig;
    float rsum[4] = {0.f, 0.f, 0.f, 0.f};
#pragma unroll
    for (int mt = 0; mt < 2; mt++) {
#pragma unroll
        for (int nt = 0; nt < 4; nt++) {
            int m = mbase + mt * 16, n = nbase + nt * 8;
            float2 v0 = __half22float2(*(__half2*)&acc[mt * 4 + nt][0]);
            float2 v1 = __half22float2(*(__half2*)&acc[mt * 4 + nt][1]);
            float e0 = __expf(v0.x * 0.0625f);
            float e1 = __expf(v0.y * 0.0625f);
            float e2 = __expf(v1.x * 0.0625f);
            float e3 = __expf(v1.y * 0.0625f);
            rsum[mt * 2 + 0] += e0 + e1;
            rsum[mt * 2 + 1] += e2 + e3;
            *(__half2*)(P + (size_t)m * CTX + n)       = __floats2half2_rn(e0, e1);
            *(__half2*)(P + (size_t)(m + 8) * CTX + n) = __floats2half2_rn(e2, e3);
        }
    }
#pragma unroll
    for (int i = 0; i < 4; i++) {
        rsum[i] += __shfl_xor_sync(0xFFFFFFFFu, rsum[i], 1);
        rsum[i] += __shfl_xor_sync(0xFFFFFFFFu, rsum[i], 2);
    }
    if (tig == 0) {
#pragma unroll
        for (int i = 0; i < 4; i++)
            atomicAdd(&ls[mbase + (i >> 1) * 16 + (i & 1) * 8], rsum[i]);
    }
    __syncthreads();
    if (t < 128)
        atomicAdd(&g_l[(size_t)(b * NB + nbi) * 128 + t], ls[t]);
}

// ---- kernel 4: att = (P @ Vc)/l (fp16), permuted. grid (4, NB, B) ---------

__global__ __launch_bounds__(256, 3)
void av_mma() {
    extern __shared__ char smbuf[];
    int t = threadIdx.x;
    int n0 = blockIdx.x * 64;
    int nbi = blockIdx.y, b = blockIdx.z;

    int lo = (nbi == 0) ? 1 : 0;
    int hi = (nbi == NB - 1) ? 1 : 2;
    int nC = (hi - lo + 1) * 2;                  // 64-token chunks
    int gb0 = nbi + lo - 1;

    const __half* Pb = g_p + (size_t)((b * NB + nbi) * BLK) * CTX + lo * BLK;
    const __half* Vt0 = g_vT + (size_t)(b * SEQ + gb0 * BLK) * EMB + (size_t)n0 * 128;

    uint32_t aA[3], bA[3];
#pragma unroll
    for (int i = 0; i < 3; i++) {
        aA[i] = smem_u32(smbuf + i * TILE128);
        bA[i] = smem_u32(smbuf + BOFF3 + i * TILE64);
    }
#pragma unroll
    for (int i = 0; i < 2; i++) {
        cpT128(aA[i], Pb + i * 64, CTX, t);
        cpT64(bA[i], Vt0 + ((size_t)(i >> 1) * BLK * EMB) + (i & 1) * 64, 128, t);
        CP_COMMIT();
    }

    float acc[8][4] = {};
    int bufc = 0, bufn = 2;
    for (int c = 0; c < nC; c++) {
        if (c < nC - 1) CP_WAIT1(); else CP_WAIT0();
        __syncthreads();
        if (c + 2 < nC) {
            int cn = c + 2;
            cpT128(aA[bufn], Pb + cn * 64, CTX, t);
            cpT64(bA[bufn], Vt0 + ((size_t)(cn >> 1) * BLK * EMB) + (cn & 1) * 64, 128, t);
            CP_COMMIT();
        }
        mma_chunk_32(aA[bufc], bA[bufc], acc, t);
        bufc = (bufc == 2) ? 0 : bufc + 1;
        bufn = (bufn == 2) ? 0 : bufn + 1;
    }

    const float* lrow = g_l + (size_t)(b * NB + nbi) * 128;
    int rowbase = nbi * (BATCH * BLK) + b * BLK;   // reference transpose (1,0,2,3)
    __half* C = g_ah + (size_t)rowbase * EMB + n0;

    int lane = t & 31, w = t >> 5;
    int g = lane >> 2, tig = lane & 3;
    int mbase = (w >> 1) * 32 + g;
    int nbase = (w & 1) * 32 + 2 * tig;
#pragma unroll
    for (int mt = 0; mt < 2; mt++) {
        int m = mbase + mt * 16;
        float inv0 = 1.0f / lrow[m];
        float inv1 = 1.0f / lrow[m + 8];
#pragma unroll
        for (int nt = 0; nt < 4; nt++) {
            float* c4 = acc[mt * 4 + nt];
            int n = nbase + nt * 8;
            *(__half2*)(C + (size_t)m * EMB + n) =
                __floats2half2_rn(c4[0] * inv0, c4[1] * inv0);
            *(__half2*)(C + (size_t)(m + 8) * EMB + n) =
                __floats2half2_rn(c4[2] * inv1, c4[3] * inv1);
        }
    }
}

// ---- kernel 5: out = att @ Wo + bo (fp32 out). grid (4, 640) --------------

__global__ __launch_bounds__(256, 3)
void out_mma(const float* __restrict__ bo, float* __restrict__ out) {
    extern __shared__ char smbuf[];
    int t = threadIdx.x;
    int n0 = blockIdx.x * 64, m0 = blockIdx.y * 128;

    float acc[8][4] = {};
    gemm3_32(g_ah + (size_t)m0 * EMB, 64, EMB,
             g_wh + (size_t)3 * EMB * EMB + (size_t)n0 * EMB, 64, EMB,
             4, acc, smbuf, t);

    const float* bias = bo + n0;
    float* C = out + (size_t)m0 * EMB + n0;
    int lane = t & 31, w = t >> 5;
    int g = lane >> 2, tig = lane & 3;
    int mbase = (w >> 1) * 32 + g;
    int nbase = (w & 1) * 32 + 2 * tig;
#pragma unroll
    for (int mt = 0; mt < 2; mt++) {
#pragma unroll
        for (int nt = 0; nt < 4; nt++) {
            float* c4 = acc[mt * 4 + nt];
            int m = mbase + mt * 16, n = nbase + nt * 8;
            float b0 = bias[n], b1 = bias[n + 1];
            *(float2*)(C + (size_t)m * EMB + n)       = make_float2(c4[0] + b0, c4[1] + b1);
            *(float2*)(C + (size_t)(m + 8) * EMB + n) = make_float2(c4[2] + b0, c4[3] + b1);
        }
    }
}

// ---- launch ---------------------------------------------------------------

extern "C" void kernel_launch(void* const* d_in, const int* in_sizes, int n_in,
                              void* d_out, int out_size) {
    const float* x  = (const float*)d_in[0];
    const float* Wq = (const float*)d_in[1];
    const float* Wk = (const float*)d_in[2];
    const float* Wv = (const float*)d_in[3];
    const float* Wo = (const float*)d_in[4];
    const float* bo = (const float*)d_in[5];
    float* out = (float*)d_out;

    cudaFuncSetAttribute(qk12_mma, cudaFuncAttributeMaxDynamicSharedMemorySize, SMEM_Q);
    cudaFuncSetAttribute(qk_mma,   cudaFuncAttributeMaxDynamicSharedMemorySize, SMEM_Q);
    cudaFuncSetAttribute(v_mma,    cudaFuncAttributeMaxDynamicSharedMemorySize, SMEM_S);
    cudaFuncSetAttribute(av_mma,   cudaFuncAttributeMaxDynamicSharedMemorySize, SMEM_S);
    cudaFuncSetAttribute(out_mma,  cudaFuncAttributeMaxDynamicSharedMemorySize, SMEM_S);

    int total = XITEMS + WITEMS + MROWS;
    cvt_all<<<(total + 255) / 256, 256>>>(x, Wq, Wk, Wv, Wo);

    qk12_mma<<<dim3(8, MROWS / 128), 256, SMEM_Q>>>();
    v_mma<<<dim3(4, MROWS / 128), 256, SMEM_S>>>();
    qk_mma<<<dim3(6, NB, BATCH), 256, SMEM_Q>>>();
    av_mma<<<dim3(4, NB, BATCH), 256, SMEM_S>>>();
    out_mma<<<dim3(4, MROWS / 128), 256, SMEM_S>>>(bo, out);
}